// round 9
// baseline (speedup 1.0000x reference)
#include <cuda_runtime.h>
#include <math.h>

#define NBLK 128
#define NTH  512
#define RPB  64
#define XP   104
#define HP   120
#define HP2  224
#define FS   40
#define WSTR 6400

#define OFF_XS   0
#define OFF_YS   6656
#define OFF_HA2  6720
#define OFF_HB   21056
#define OFF_WB   28736
#define OFF_AFA  40836
#define OFF_AFC  40964
#define OFF_WC   41092
#define SMEM_FLOATS 53892
#define SMEM_BYTES  (SMEM_FLOATS * 4)

__device__ __align__(16) float g_sum[63][4][128 * FS];
__device__ __align__(16) float g_ss2[63][4][128 * FS];
__device__ __align__(16) unsigned g_flags[NBLK * 32];
__device__ unsigned g_release;
__device__ __align__(32) unsigned g_arr[253][8];    // 8 sharded counters / round
__device__ __align__(32) unsigned g_arrY[63][8];

__device__ __forceinline__ void gridbar(unsigned gen) {
    __syncthreads();
    if (threadIdx.x == 0) {
        __threadfence();
        *(volatile unsigned*)&g_flags[blockIdx.x * 32] = gen;
    }
    if (blockIdx.x == 0) {
        if (threadIdx.x < NBLK) {
            volatile unsigned* fp = &g_flags[threadIdx.x * 32];
            while (*fp < gen) {}
        }
        __syncthreads();
        if (threadIdx.x == 0) { __threadfence(); *(volatile unsigned*)&g_release = gen; }
        __syncthreads();
    } else {
        if (threadIdx.x == 0) {
            volatile unsigned* rp = &g_release;
            while (*rp < gen) {}
            __threadfence();
        }
        __syncthreads();
    }
}

// sharded arrive/wait: 8 counters in one 32B line
__device__ __forceinline__ void arrive8(unsigned* base) {
    __threadfence();
    asm volatile("red.global.add.u32 [%0], 1;" :: "l"(base + (blockIdx.x & 7)) : "memory");
}
__device__ __forceinline__ void wait8(const unsigned* base) {
    const uint4* p = (const uint4*)base;
    for (;;) {
        uint4 a = __ldcg(p), b = __ldcg(p + 1);
        if (a.x + a.y + a.z + a.w + b.x + b.y + b.z + b.w >= NBLK) break;
    }
    __threadfence();
}

__device__ __forceinline__ void cp_async16(float* dst_smem, const float* src) {
    unsigned d = (unsigned)__cvta_generic_to_shared(dst_smem);
    asm volatile("cp.async.cg.shared.global [%0], [%1], 16;\n" :: "r"(d), "l"(src));
}
__device__ __forceinline__ void cp_commit() { asm volatile("cp.async.commit_group;\n"); }
__device__ __forceinline__ void cp_wait0()  { asm volatile("cp.async.wait_group 0;\n" ::: "memory"); }

#define FMA2(acc, a, b) asm("fma.rn.f32x2 %0, %1, %2, %0;" : "+l"(acc) : "l"(a), "l"(b))

__device__ __forceinline__ float my_sin(float x) {
    float kf = rintf(x * 0.63661977236758134f);
    int k = (int)kf;
    float r = fmaf(-kf, 1.57079637050628662f, x);
    r = fmaf(-kf, -4.37113900018624283e-8f, r);
    float r2 = r * r;
    float sp = fmaf(r2, 2.7557314e-6f, -1.9841270e-4f);
    sp = fmaf(r2, sp, 8.3333331e-3f);
    sp = fmaf(r2, sp, -1.6666667e-1f);
    sp = r * fmaf(r2, sp, 1.0f);
    float cp = fmaf(r2, 2.4801587e-5f, -1.3888889e-3f);
    cp = fmaf(r2, cp, 4.1666666e-2f);
    cp = fmaf(r2, cp, -0.5f);
    cp = fmaf(r2, cp, 1.0f);
    int kk = k & 3;
    float res = (kk & 1) ? cp : sp;
    if (kk >= 2) res = -res;
    return res;
}

__device__ __forceinline__ void affine_one(const float* gs, const float* gq,
                                           float gamma, float beta, int f,
                                           float* a_out, float* c_out) {
    float4 a0 = __ldcg((const float4*)&gs[f * FS]);
    float4 a1 = __ldcg((const float4*)&gs[f * FS + 4]);
    float4 b0 = __ldcg((const float4*)&gq[f * FS]);
    float4 b1 = __ldcg((const float4*)&gq[f * FS + 4]);
    float mu  = (((a0.x + a0.y) + (a0.z + a0.w)) + ((a1.x + a1.y) + (a1.z + a1.w))) * (1.f / 8192.f);
    float ex2 = (((b0.x + b0.y) + (b0.z + b0.w)) + ((b1.x + b1.y) + (b1.z + b1.w))) * (1.f / 8192.f);
    float v = fmaxf(ex2 - mu * mu, 0.f) + 1e-6f;
    float rs = rsqrtf(v);
    rs = rs * (1.5f - 0.5f * v * rs * rs);
    float a = gamma * rs;
    *a_out = a;
    *c_out = fmaf(-a, mu, beta);
}

__device__ __forceinline__ void make_affine(const float* gs, const float* gq,
                                            const float* __restrict__ gamma,
                                            const float* __restrict__ beta,
                                            int nf, float* affA, float* affC) {
    int f = threadIdx.x;
    if (f < nf) {
        float a, c;
        affine_one(gs, gq, gamma[f], beta[f], f, &a, &c);
        affA[f] = a; affC[f] = c;
    }
}

__device__ __forceinline__ void stats128(const float* buf, int pitch, int nf,
                                         float* gs, float* gq) {
    int f = threadIdx.x;
    if (f < nf) {
        float s1 = 0.f, s2 = 0.f;
        const float* p = buf + f;
#pragma unroll 8
        for (int r = 0; r < RPB; r++) { float v = p[r * pitch]; s1 += v; s2 = fmaf(v, v, s2); }
        int sh = blockIdx.x & 7;
        atomicAdd(&gs[f * FS + sh], s1);
        atomicAdd(&gq[f * FS + sh], s2);
    }
}

// k-paired FFMA2 GEMM. W staged as quads: offset(k,j)=(k>>1)*2*NC+(j>>1)*4+(k&1)*2+(j&1)
template<int KP, int NC>
__device__ __forceinline__ void gemm_pairs(unsigned long long acc[4][4],
                                           const float* __restrict__ A,
                                           const float* __restrict__ wm) {
    int rg = threadIdx.x >> 4, cg = threadIdx.x & 15;
    int r0 = rg * 4;
    const ulonglong2* a0 = (const ulonglong2*)(A + r0 * HP2);
    const ulonglong2* a1 = (const ulonglong2*)(A + (r0 + 1) * HP2);
    const ulonglong2* a2 = (const ulonglong2*)(A + (r0 + 2) * HP2);
    const ulonglong2* a3 = (const ulonglong2*)(A + (r0 + 3) * HP2);
#pragma unroll 2
    for (int p = 0; p < KP; p++) {
        ulonglong2 A0 = a0[p], A1 = a1[p], A2 = a2[p], A3 = a3[p];
        const ulonglong2* wr = (const ulonglong2*)(wm + p * 2 * NC) + cg;
#pragma unroll
        for (int v = 0; v < 4; v++) {
            ulonglong2 wv = wr[v * 16];
            FMA2(acc[0][v], A0.x, wv.x);
            FMA2(acc[1][v], A1.x, wv.x);
            FMA2(acc[2][v], A2.x, wv.x);
            FMA2(acc[3][v], A3.x, wv.x);
            FMA2(acc[0][v], A0.y, wv.y);
            FMA2(acc[1][v], A1.y, wv.y);
            FMA2(acc[2][v], A2.y, wv.y);
            FMA2(acc[3][v], A3.y, wv.y);
        }
    }
}

// single-k tail (linear W row), A dup-pair at column k
__device__ __forceinline__ void gemm_k(unsigned long long acc[4][4],
                                       const float* __restrict__ A,
                                       const float* __restrict__ wrow,
                                       int r0, int cg, int k) {
    unsigned long long X0 = ((const unsigned long long*)(A + r0 * HP2))[k];
    unsigned long long X1 = ((const unsigned long long*)(A + (r0 + 1) * HP2))[k];
    unsigned long long X2 = ((const unsigned long long*)(A + (r0 + 2) * HP2))[k];
    unsigned long long X3 = ((const unsigned long long*)(A + (r0 + 3) * HP2))[k];
    const unsigned long long* wr = (const unsigned long long*)wrow + cg;
#pragma unroll
    for (int v = 0; v < 4; v++) {
        unsigned long long wv = wr[v * 16];
        FMA2(acc[0][v], X0, wv);
        FMA2(acc[1][v], X1, wv);
        FMA2(acc[2][v], X2, wv);
        FMA2(acc[3][v], X3, wv);
    }
}

template<int NC>
__device__ __forceinline__ void gemm_store(unsigned long long acc[4][4],
                                           float* __restrict__ dst) {
    int rg = threadIdx.x >> 4, cg = threadIdx.x & 15;
    int r0 = rg * 4;
#pragma unroll
    for (int v = 0; v < 4; v++) {
        int j = cg * 2 + v * 32;
        if (j + 1 < NC) {
#pragma unroll
            for (int i = 0; i < 4; i++)
                *(float2*)&dst[(r0 + i) * HP + j] = *(float2*)&acc[i][v];
        }
    }
}

__device__ __forceinline__ void prefetch_W256(float* Wcbuf, const float* W, int row0, int t0) {
    int t = threadIdx.x - 256;
    for (int i = t; i < RPB * 25; i += 256) {
        int r = i & 63, c = i >> 6;
        cp_async16(Wcbuf + r * 100 + c * 4,
                   W + ((size_t)(row0 + r) * 64 + t0) * 100 + c * 4);
    }
    cp_commit();
}

__global__ void __launch_bounds__(NTH, 1)
fullnn(const float* __restrict__ W,
       const float* __restrict__ y_init, const float* __restrict__ z_init,
       const float* __restrict__ g0, const float* __restrict__ b0,
       const float* __restrict__ g1, const float* __restrict__ b1,
       const float* __restrict__ g2, const float* __restrict__ b2,
       const float* __restrict__ g3, const float* __restrict__ b3,
       const float* __restrict__ w0, const float* __restrict__ w1,
       const float* __restrict__ w2,
       float* __restrict__ out)
{
    extern __shared__ float sm[];
    float* xs   = sm + OFF_XS;
    float* ys   = sm + OFF_YS;
    float* hA2  = sm + OFF_HA2;
    float* hB   = sm + OFF_HB;
    float* wb   = sm + OFF_WB;
    float* affA = sm + OFF_AFA;
    float* affC = sm + OFF_AFC;
    float* Wc   = sm + OFF_WC;

    const int tid  = threadIdx.x;
    const int bk   = blockIdx.x;
    const int row0 = bk * RPB;
    const int r_ = tid >> 3, q_ = tid & 7;
    const int fA = tid & 127, rbA = tid >> 7;

    unsigned gen = *(volatile unsigned*)&g_release;

    for (int i = tid; i < RPB * 25; i += NTH) {
        int r = i & 63, c = i >> 6;
        cp_async16(Wc + r * 100 + c * 4, W + ((size_t)(row0 + r) * 64 + 0) * 100 + c * 4);
        cp_async16(Wc + WSTR + r * 100 + c * 4, W + ((size_t)(row0 + r) * 64 + 1) * 100 + c * 4);
    }
    cp_commit();

    {   // zero stats + counters
        float4* p1 = (float4*)&g_sum[0][0][0];
        float4* p2 = (float4*)&g_ss2[0][0][0];
        int n4 = 63 * 4 * 128 * FS / 4;
        for (int i = bk * NTH + tid; i < n4; i += NBLK * NTH) {
            p1[i] = make_float4(0.f, 0.f, 0.f, 0.f);
            p2[i] = make_float4(0.f, 0.f, 0.f, 0.f);
        }
        if (bk == 0) {
            for (int i = tid; i < 253 * 8; i += NTH) (&g_arr[0][0])[i] = 0u;
            for (int i = tid; i < 63 * 8; i += NTH) (&g_arrY[0][0])[i] = 0u;
        }
    }
    const float y0v = y_init[0];
    const float z0v = z_init[0];
    for (int i = tid; i < RPB * 100; i += NTH) {
        int r = i / 100, d = i - r * 100;
        xs[r * XP + d] = 1.57079632679489662f;
    }
    for (int r = tid; r < RPB; r += NTH) ys[r] = y0v;
    cp_wait0();
    gridbar(++gen);

    for (int s = 0; s < 63; s++) {
        const int base = s * 4;
        // ---- 1: x update + sin
        cp_wait0();
        __syncthreads();
        float ssin = 0.f;
        {
            const float yold = ys[r_];
            const float* Wold = Wc + (s & 1) * WSTR + r_ * 100;
            const float* Wnew = Wc + ((s + 1) & 1) * WSTR + r_ * 100;
#pragma unroll 13
            for (int d = q_; d < 100; d += 8) {
                float dw = Wnew[d] - Wold[d];
                float xn = fmaf(0.3f * dw, yold, xs[r_ * XP + d]);
                xs[r_ * XP + d] = xn;
                ssin += my_sin(xn);
            }
        }
        __syncthreads();
        // ---- 2: x-stats push || stage w0 (k-paired layout; row 100 linear at 11000)
        if (tid < 100) {
            float s1 = 0.f, s2 = 0.f;
            const float* p = xs + tid;
#pragma unroll 8
            for (int r = 0; r < RPB; r++) { float v = p[r * XP]; s1 += v; s2 = fmaf(v, v, s2); }
            int sh = bk & 7;
            atomicAdd(&g_sum[s][0][tid * FS + sh], s1);
            atomicAdd(&g_ss2[s][0][tid * FS + sh], s2);
        } else if (tid >= 128) {
            const float2* src = (const float2*)(w0 + (size_t)s * 11110);
            for (int i = tid - 128; i < 5555; i += 384) {
                int k = i / 55, jh = i - k * 55;
                float2 v = src[i];
                int dst = (k < 100) ? ((k >> 1) * 220 + jh * 4 + (k & 1) * 2)
                                    : (11000 + jh * 2);
                *(float2*)&wb[dst] = v;
            }
        }
        __syncthreads();
        if (tid == 0) arrive8(g_arr[base + 0]);
        // ---- 3: wait stats3(s-1), BN3 affine
        if (s > 0) {
            if (tid == 0) wait8(g_arr[base - 1]);
            __syncthreads();
            make_affine(g_sum[s-1][3], g_ss2[s-1][3], g3 + (s-1)*100, b3 + (s-1)*100, 100, affA, affC);
        }
        __syncthreads();
        // ---- 4: zdot + y update
        {
            const float ec = expf(-0.3f * (1.0f - (float)s * (1.0f / 64.0f)));
            const float yold = ys[r_];
            const float* Wold = Wc + (s & 1) * WSTR + r_ * 100;
            const float* Wnew = Wc + ((s + 1) & 1) * WSTR + r_ * 100;
            float zdot = 0.f;
#pragma unroll 13
            for (int d = q_; d < 100; d += 8) {
                float dw = Wnew[d] - Wold[d];
                float zv = (s == 0) ? z0v : fmaf(affA[d], hB[r_ * HP + d], affC[d]) * 0.01f;
                zdot = fmaf(zv, dw, zdot);
            }
            ssin += __shfl_xor_sync(0xffffffffu, ssin, 1);
            ssin += __shfl_xor_sync(0xffffffffu, ssin, 2);
            ssin += __shfl_xor_sync(0xffffffffu, ssin, 4);
            zdot += __shfl_xor_sync(0xffffffffu, zdot, 1);
            zdot += __shfl_xor_sync(0xffffffffu, zdot, 2);
            zdot += __shfl_xor_sync(0xffffffffu, zdot, 4);
            if (q_ == 0) {
                float tc = 0.1f * ssin;
                float dr = fmaf(-0.1f, yold, 0.045f * ec * tc * tc * tc);
                ys[r_] = yold - dr * (1.0f / 64.0f) + zdot;
            }
        }
        __syncthreads();
        // ---- 5: warp1 y-stat + arriveY ; tid0 waits x-stats
        if (tid >= 32 && tid < 64) {
            int l = tid - 32;
            float v0 = ys[2 * l], v1 = ys[2 * l + 1];
            float s1 = v0 + v1;
            float s2 = fmaf(v0, v0, v1 * v1);
            for (int o = 16; o > 0; o >>= 1) {
                s1 += __shfl_xor_sync(0xffffffffu, s1, o);
                s2 += __shfl_xor_sync(0xffffffffu, s2, o);
            }
            if (l == 0) {
                int sh = bk & 7;
                atomicAdd(&g_sum[s][0][100 * FS + sh], s1);
                atomicAdd(&g_ss2[s][0][100 * FS + sh], s2);
                arrive8(g_arrY[s]);
            }
        }
        if (tid == 0) wait8(g_arr[base + 0]);
        __syncthreads();
        // ---- 6: BN0 affine (x) + apply x cols
        make_affine(g_sum[s][0], g_ss2[s][0], g0 + s*101, b0 + s*101, 100, affA, affC);
        __syncthreads();
        if (fA < 100) {
            float a = affA[fA], c = affC[fA];
#pragma unroll
            for (int i = 0; i < 16; i++) {
                int r = rbA + 4 * i;
                float v = fmaf(a, xs[r * XP + fA], c);
                *(float2*)&hA2[r * HP2 + 2 * fA] = make_float2(v, v);
            }
        }
        __syncthreads();
        // ---- 7: GEMM0 main (50 k-pairs) || y-path waits + applies col 100
        unsigned long long acc[4][4] = {};
        if (tid < 256) {
            gemm_pairs<50, 110>(acc, hA2, wb);
        } else if (tid < 320) {
            int t = tid - 256;
            wait8(g_arrY[s]);
            float a, c;
            affine_one(g_sum[s][0], g_ss2[s][0], g0[s*101 + 100], b0[s*101 + 100], 100, &a, &c);
            float v = fmaf(a, ys[t], c);
            *(float2*)&hA2[t * HP2 + 200] = make_float2(v, v);
        }
        __syncthreads();
        // ---- 8: GEMM0 tail k=100 + store
        if (tid < 256) {
            gemm_k(acc, hA2, wb + 11000, (tid >> 4) * 4, tid & 15, 100);
            gemm_store<110>(acc, hB);
        }
        __syncthreads();
        // ---- 9: stats1 || copy w1 (paired layout)
        if (tid < 128) stats128(hB, HP, 110, g_sum[s][1], g_ss2[s][1]);
        else if (tid >= 256) {
            const float2* src = (const float2*)(w1 + (size_t)s * 12100);
            for (int i = tid - 256; i < 6050; i += 256) {
                int k = i / 55, jh = i - k * 55;
                float2 v = src[i];
                *(float2*)&wb[(k >> 1) * 220 + jh * 4 + (k & 1) * 2] = v;
            }
        }
        __syncthreads();
        if (tid == 0) { arrive8(g_arr[base + 1]); wait8(g_arr[base + 1]); }
        __syncthreads();
        // ---- Phase C: BN1+relu, GEMM1, stats2 || copy w2 (paired)
        make_affine(g_sum[s][1], g_ss2[s][1], g1 + s*110, b1 + s*110, 110, affA, affC);
        __syncthreads();
        if (fA < 110) {
            float a = affA[fA], c = affC[fA];
#pragma unroll
            for (int i = 0; i < 16; i++) {
                int r = rbA + 4 * i;
                float v = fmaxf(fmaf(a, hB[r * HP + fA], c), 0.f);
                *(float2*)&hA2[r * HP2 + 2 * fA] = make_float2(v, v);
            }
        }
        __syncthreads();
        if (tid < 256) {
            unsigned long long acc1[4][4] = {};
            gemm_pairs<55, 110>(acc1, hA2, wb);
            gemm_store<110>(acc1, hB);
        }
        __syncthreads();
        if (tid < 128) stats128(hB, HP, 110, g_sum[s][2], g_ss2[s][2]);
        else if (tid >= 256) {
            const float2* src = (const float2*)(w2 + (size_t)s * 11000);
            for (int i = tid - 256; i < 5500; i += 256) {
                int k = i / 50, jh = i - k * 50;
                float2 v = src[i];
                *(float2*)&wb[(k >> 1) * 200 + jh * 4 + (k & 1) * 2] = v;
            }
        }
        __syncthreads();
        if (tid == 0) { arrive8(g_arr[base + 2]); wait8(g_arr[base + 2]); }
        __syncthreads();
        // ---- Phase D: BN2+relu, GEMM2 || prefetch W, stats3, arrive
        make_affine(g_sum[s][2], g_ss2[s][2], g2 + s*110, b2 + s*110, 110, affA, affC);
        __syncthreads();
        if (fA < 110) {
            float a = affA[fA], c = affC[fA];
#pragma unroll
            for (int i = 0; i < 16; i++) {
                int r = rbA + 4 * i;
                float v = fmaxf(fmaf(a, hB[r * HP + fA], c), 0.f);
                *(float2*)&hA2[r * HP2 + 2 * fA] = make_float2(v, v);
            }
        }
        __syncthreads();
        if (tid < 256) {
            unsigned long long acc2[4][4] = {};
            gemm_pairs<55, 100>(acc2, hA2, wb);
            gemm_store<100>(acc2, hB);
        } else if (s <= 61) prefetch_W256(Wc + (s & 1) * WSTR, W, row0, s + 2);
        __syncthreads();
        if (tid < 128) stats128(hB, HP, 100, g_sum[s][3], g_ss2[s][3]);
        __syncthreads();
        if (tid == 0) arrive8(g_arr[base + 3]);
    }

    // ---- Final extra step; write outputs
    if (tid == 0) wait8(g_arr[62 * 4 + 3]);
    __syncthreads();
    make_affine(g_sum[62][3], g_ss2[62][3], g3 + 62*100, b3 + 62*100, 100, affA, affC);
    __syncthreads();
    {
        float ec = expf(-0.3f * (1.0f - 62.0f / 64.0f));
        float yold = ys[r_];
        const float* Wold = Wc + r_ * 100;
        const float* Wnew = Wc + WSTR + r_ * 100;
        float ssin = 0.f, zdot = 0.f;
        for (int d = q_; d < 100; d += 8) {
            float dw = Wnew[d] - Wold[d];
            float xn = fmaf(0.3f * dw, yold, xs[r_ * XP + d]);
            out[(size_t)(row0 + r_) * 100 + d] = xn;
            ssin += my_sin(xn);
            float zv = fmaf(affA[d], hB[r_ * HP + d], affC[d]) * 0.01f;
            zdot = fmaf(zv, dw, zdot);
        }
        ssin += __shfl_xor_sync(0xffffffffu, ssin, 1);
        ssin += __shfl_xor_sync(0xffffffffu, ssin, 2);
        ssin += __shfl_xor_sync(0xffffffffu, ssin, 4);
        zdot += __shfl_xor_sync(0xffffffffu, zdot, 1);
        zdot += __shfl_xor_sync(0xffffffffu, zdot, 2);
        zdot += __shfl_xor_sync(0xffffffffu, zdot, 4);
        if (q_ == 0) {
            float tc = 0.1f * ssin;
            float dr = fmaf(-0.1f, yold, 0.045f * ec * tc * tc * tc);
            out[(size_t)8192 * 100 + row0 + r_] = yold - dr * (1.0f / 64.0f) + zdot;
        }
    }
}

extern "C" void kernel_launch(void* const* d_in, const int* in_sizes, int n_in,
                              void* d_out, int out_size) {
    cudaFuncSetAttribute(fullnn, cudaFuncAttributeMaxDynamicSharedMemorySize, SMEM_BYTES);
    fullnn<<<NBLK, NTH, SMEM_BYTES>>>(
        (const float*)d_in[0], (const float*)d_in[1], (const float*)d_in[2],
        (const float*)d_in[3], (const float*)d_in[4], (const float*)d_in[5],
        (const float*)d_in[6], (const float*)d_in[7], (const float*)d_in[8],
        (const float*)d_in[9], (const float*)d_in[10], (const float*)d_in[11],
        (const float*)d_in[12], (const float*)d_in[13],
        (float*)d_out);
}

// round 10
// speedup vs baseline: 1.0953x; 1.0953x over previous
#include <cuda_runtime.h>
#include <math.h>

#define NBLK 128
#define NTH  512
#define RPB  64
#define XP   104
#define HP   120
#define HP2  224
#define FS   40
#define WSTR 6400

#define OFF_XS   0
#define OFF_YS   6656
#define OFF_HA2  6720
#define OFF_HB   21056
#define OFF_WB   28736
#define OFF_AFA  40836
#define OFF_AFC  40964
#define OFF_WC   41092
#define SMEM_FLOATS 53892
#define SMEM_BYTES  (SMEM_FLOATS * 4)

__device__ __align__(16) float g_sum[63][4][128 * FS];
__device__ __align__(16) float g_ss2[63][4][128 * FS];
__device__ __align__(16) unsigned g_flags[NBLK * 32];
__device__ unsigned g_release;
__device__ __align__(32) unsigned g_arr[253][8];   // 8 sharded counters per round
__device__ __align__(32) unsigned g_arrY[63][8];

__device__ __forceinline__ void gridbar(unsigned gen) {
    __syncthreads();
    if (threadIdx.x == 0) {
        __threadfence();
        *(volatile unsigned*)&g_flags[blockIdx.x * 32] = gen;
    }
    if (blockIdx.x == 0) {
        if (threadIdx.x < NBLK) {
            volatile unsigned* fp = &g_flags[threadIdx.x * 32];
            while (*fp < gen) {}
        }
        __syncthreads();
        if (threadIdx.x == 0) { __threadfence(); *(volatile unsigned*)&g_release = gen; }
        __syncthreads();
    } else {
        if (threadIdx.x == 0) {
            volatile unsigned* rp = &g_release;
            while (*rp < gen) {}
            __threadfence();
        }
        __syncthreads();
    }
}

// sharded arrive/wait: 8 counters in one 32B line
__device__ __forceinline__ void arrive8(unsigned* base) {
    __threadfence();
    asm volatile("red.global.add.u32 [%0], 1;" :: "l"(base + (blockIdx.x & 7)) : "memory");
}
__device__ __forceinline__ void wait8(const unsigned* base) {
    const uint4* p = (const uint4*)base;
    for (;;) {
        uint4 a = __ldcg(p), b = __ldcg(p + 1);
        if (a.x + a.y + a.z + a.w + b.x + b.y + b.z + b.w >= NBLK) break;
    }
    __threadfence();
}

__device__ __forceinline__ void cp_async16(float* dst_smem, const float* src) {
    unsigned d = (unsigned)__cvta_generic_to_shared(dst_smem);
    asm volatile("cp.async.cg.shared.global [%0], [%1], 16;\n" :: "r"(d), "l"(src));
}
__device__ __forceinline__ void cp_commit() { asm volatile("cp.async.commit_group;\n"); }
__device__ __forceinline__ void cp_wait0()  { asm volatile("cp.async.wait_group 0;\n" ::: "memory"); }

#define FMA2(acc, a, b) asm("fma.rn.f32x2 %0, %1, %2, %0;" : "+l"(acc) : "l"(a), "l"(b))

__device__ __forceinline__ float my_sin(float x) {
    float kf = rintf(x * 0.63661977236758134f);
    int k = (int)kf;
    float r = fmaf(-kf, 1.57079637050628662f, x);
    r = fmaf(-kf, -4.37113900018624283e-8f, r);
    float r2 = r * r;
    float sp = fmaf(r2, 2.7557314e-6f, -1.9841270e-4f);
    sp = fmaf(r2, sp, 8.3333331e-3f);
    sp = fmaf(r2, sp, -1.6666667e-1f);
    sp = r * fmaf(r2, sp, 1.0f);
    float cp = fmaf(r2, 2.4801587e-5f, -1.3888889e-3f);
    cp = fmaf(r2, cp, 4.1666666e-2f);
    cp = fmaf(r2, cp, -0.5f);
    cp = fmaf(r2, cp, 1.0f);
    int kk = k & 3;
    float res = (kk & 1) ? cp : sp;
    if (kk >= 2) res = -res;
    return res;
}

__device__ __forceinline__ void affine_one(const float* gs, const float* gq,
                                           float gamma, float beta, int f,
                                           float* a_out, float* c_out) {
    float4 a0 = __ldcg((const float4*)&gs[f * FS]);
    float4 a1 = __ldcg((const float4*)&gs[f * FS + 4]);
    float4 b0 = __ldcg((const float4*)&gq[f * FS]);
    float4 b1 = __ldcg((const float4*)&gq[f * FS + 4]);
    float mu  = (((a0.x + a0.y) + (a0.z + a0.w)) + ((a1.x + a1.y) + (a1.z + a1.w))) * (1.f / 8192.f);
    float ex2 = (((b0.x + b0.y) + (b0.z + b0.w)) + ((b1.x + b1.y) + (b1.z + b1.w))) * (1.f / 8192.f);
    float v = fmaxf(ex2 - mu * mu, 0.f) + 1e-6f;
    float rs = rsqrtf(v);
    rs = rs * (1.5f - 0.5f * v * rs * rs);
    float a = gamma * rs;
    *a_out = a;
    *c_out = fmaf(-a, mu, beta);
}

__device__ __forceinline__ void make_affine(const float* gs, const float* gq,
                                            const float* __restrict__ gamma,
                                            const float* __restrict__ beta,
                                            int nf, float* affA, float* affC) {
    int f = threadIdx.x;
    if (f < nf) {
        float a, c;
        affine_one(gs, gq, gamma[f], beta[f], f, &a, &c);
        affA[f] = a; affC[f] = c;
    }
}

__device__ __forceinline__ void stats128(const float* buf, int pitch, int nf,
                                         float* gs, float* gq) {
    int f = threadIdx.x;
    if (f < nf) {
        float s1 = 0.f, s2 = 0.f;
        const float* p = buf + f;
#pragma unroll 8
        for (int r = 0; r < RPB; r++) { float v = p[r * pitch]; s1 += v; s2 = fmaf(v, v, s2); }
        int sh = blockIdx.x & 7;
        atomicAdd(&gs[f * FS + sh], s1);
        atomicAdd(&gq[f * FS + sh], s2);
    }
}

// FFMA2 GEMM pieces (R8 version: linear W layout, LDS.64). tid<256.
__device__ __forceinline__ void gemm_k(unsigned long long acc[4][4],
                                       const float* __restrict__ A,
                                       const float* __restrict__ wrow,
                                       int r0, int cg, int k) {
    unsigned long long X0 = ((const unsigned long long*)(A + r0 * HP2))[k];
    unsigned long long X1 = ((const unsigned long long*)(A + (r0 + 1) * HP2))[k];
    unsigned long long X2 = ((const unsigned long long*)(A + (r0 + 2) * HP2))[k];
    unsigned long long X3 = ((const unsigned long long*)(A + (r0 + 3) * HP2))[k];
    const unsigned long long* wr = (const unsigned long long*)wrow + cg;
#pragma unroll
    for (int v = 0; v < 4; v++) {
        unsigned long long wv = wr[v * 16];
        FMA2(acc[0][v], X0, wv);
        FMA2(acc[1][v], X1, wv);
        FMA2(acc[2][v], X2, wv);
        FMA2(acc[3][v], X3, wv);
    }
}

template<int K, int NC>
__device__ __forceinline__ void gemm_main(unsigned long long acc[4][4],
                                          const float* __restrict__ A,
                                          const float* __restrict__ wm) {
    int rg = threadIdx.x >> 4, cg = threadIdx.x & 15;
    int r0 = rg * 4;
#pragma unroll 2
    for (int k = 0; k < K; k++)
        gemm_k(acc, A, wm + k * NC, r0, cg, k);
}

template<int NC>
__device__ __forceinline__ void gemm_store(unsigned long long acc[4][4],
                                           float* __restrict__ dst) {
    int rg = threadIdx.x >> 4, cg = threadIdx.x & 15;
    int r0 = rg * 4;
#pragma unroll
    for (int v = 0; v < 4; v++) {
        int j = cg * 2 + v * 32;
        if (j + 1 < NC) {
#pragma unroll
            for (int i = 0; i < 4; i++)
                *(float2*)&dst[(r0 + i) * HP + j] = *(float2*)&acc[i][v];
        }
    }
}

template<int K, int NC>
__device__ __forceinline__ void gemm64(const float* __restrict__ A,
                                       const float* __restrict__ wm,
                                       float* __restrict__ dst) {
    unsigned long long acc[4][4] = {};
    gemm_main<K, NC>(acc, A, wm);
    gemm_store<NC>(acc, dst);
}

__device__ __forceinline__ void prefetch_W256(float* Wcbuf, const float* W, int row0, int t0) {
    int t = threadIdx.x - 256;
    for (int i = t; i < RPB * 25; i += 256) {
        int r = i & 63, c = i >> 6;
        cp_async16(Wcbuf + r * 100 + c * 4,
                   W + ((size_t)(row0 + r) * 64 + t0) * 100 + c * 4);
    }
    cp_commit();
}

__global__ void __launch_bounds__(NTH, 1)
fullnn(const float* __restrict__ W,
       const float* __restrict__ y_init, const float* __restrict__ z_init,
       const float* __restrict__ g0, const float* __restrict__ b0,
       const float* __restrict__ g1, const float* __restrict__ b1,
       const float* __restrict__ g2, const float* __restrict__ b2,
       const float* __restrict__ g3, const float* __restrict__ b3,
       const float* __restrict__ w0, const float* __restrict__ w1,
       const float* __restrict__ w2,
       float* __restrict__ out)
{
    extern __shared__ float sm[];
    float* xs   = sm + OFF_XS;
    float* ys   = sm + OFF_YS;
    float* hA2  = sm + OFF_HA2;
    float* hB   = sm + OFF_HB;
    float* wb   = sm + OFF_WB;
    float* affA = sm + OFF_AFA;
    float* affC = sm + OFF_AFC;
    float* Wc   = sm + OFF_WC;

    const int tid  = threadIdx.x;
    const int bk   = blockIdx.x;
    const int row0 = bk * RPB;
    const int r_ = tid >> 3, q_ = tid & 7;
    const int fA = tid & 127, rbA = tid >> 7;

    unsigned gen = *(volatile unsigned*)&g_release;

    for (int i = tid; i < RPB * 25; i += NTH) {
        int r = i & 63, c = i >> 6;
        cp_async16(Wc + r * 100 + c * 4, W + ((size_t)(row0 + r) * 64 + 0) * 100 + c * 4);
        cp_async16(Wc + WSTR + r * 100 + c * 4, W + ((size_t)(row0 + r) * 64 + 1) * 100 + c * 4);
    }
    cp_commit();

    {   // zero stats + counters
        float4* p1 = (float4*)&g_sum[0][0][0];
        float4* p2 = (float4*)&g_ss2[0][0][0];
        int n4 = 63 * 4 * 128 * FS / 4;
        for (int i = bk * NTH + tid; i < n4; i += NBLK * NTH) {
            p1[i] = make_float4(0.f, 0.f, 0.f, 0.f);
            p2[i] = make_float4(0.f, 0.f, 0.f, 0.f);
        }
        if (bk == 0) {
            for (int i = tid; i < 253 * 8; i += NTH) (&g_arr[0][0])[i] = 0u;
            for (int i = tid; i < 63 * 8; i += NTH) (&g_arrY[0][0])[i] = 0u;
        }
    }
    const float y0v = y_init[0];
    const float z0v = z_init[0];
    for (int i = tid; i < RPB * 100; i += NTH) {
        int r = i / 100, d = i - r * 100;
        xs[r * XP + d] = 1.57079632679489662f;
    }
    for (int r = tid; r < RPB; r += NTH) ys[r] = y0v;
    cp_wait0();
    gridbar(++gen);

    for (int s = 0; s < 63; s++) {
        const int base = s * 4;
        // ---- 1: x update + sin (no global deps)
        cp_wait0();
        __syncthreads();
        float ssin = 0.f;
        {
            const float yold = ys[r_];
            const float* Wold = Wc + (s & 1) * WSTR + r_ * 100;
            const float* Wnew = Wc + ((s + 1) & 1) * WSTR + r_ * 100;
#pragma unroll 13
            for (int d = q_; d < 100; d += 8) {
                float dw = Wnew[d] - Wold[d];
                float xn = fmaf(0.3f * dw, yold, xs[r_ * XP + d]);
                xs[r_ * XP + d] = xn;
                ssin += my_sin(xn);
            }
        }
        __syncthreads();
        // ---- 2: push x-stats early || stage w0
        if (tid < 100) {
            float s1 = 0.f, s2 = 0.f;
            const float* p = xs + tid;
#pragma unroll 8
            for (int r = 0; r < RPB; r++) { float v = p[r * XP]; s1 += v; s2 = fmaf(v, v, s2); }
            int sh = bk & 7;
            atomicAdd(&g_sum[s][0][tid * FS + sh], s1);
            atomicAdd(&g_ss2[s][0][tid * FS + sh], s2);
        } else if (tid >= 128) {
            const float2* src = (const float2*)(w0 + (size_t)s * 11110);
            float2* dst = (float2*)wb;
            for (int i = tid - 128; i < 5555; i += 384) dst[i] = src[i];
        }
        __syncthreads();
        if (tid == 0) arrive8(g_arr[base + 0]);
        // ---- 3: wait stats3(s-1), BN3 affine
        if (s > 0) {
            if (tid == 0) wait8(g_arr[base - 1]);
            __syncthreads();
            make_affine(g_sum[s-1][3], g_ss2[s-1][3], g3 + (s-1)*100, b3 + (s-1)*100, 100, affA, affC);
        }
        __syncthreads();
        // ---- 4: zdot + y update
        {
            const float ec = expf(-0.3f * (1.0f - (float)s * (1.0f / 64.0f)));
            const float yold = ys[r_];
            const float* Wold = Wc + (s & 1) * WSTR + r_ * 100;
            const float* Wnew = Wc + ((s + 1) & 1) * WSTR + r_ * 100;
            float zdot = 0.f;
#pragma unroll 13
            for (int d = q_; d < 100; d += 8) {
                float dw = Wnew[d] - Wold[d];
                float zv = (s == 0) ? z0v : fmaf(affA[d], hB[r_ * HP + d], affC[d]) * 0.01f;
                zdot = fmaf(zv, dw, zdot);
            }
            ssin += __shfl_xor_sync(0xffffffffu, ssin, 1);
            ssin += __shfl_xor_sync(0xffffffffu, ssin, 2);
            ssin += __shfl_xor_sync(0xffffffffu, ssin, 4);
            zdot += __shfl_xor_sync(0xffffffffu, zdot, 1);
            zdot += __shfl_xor_sync(0xffffffffu, zdot, 2);
            zdot += __shfl_xor_sync(0xffffffffu, zdot, 4);
            if (q_ == 0) {
                float tc = 0.1f * ssin;
                float dr = fmaf(-0.1f, yold, 0.045f * ec * tc * tc * tc);
                ys[r_] = yold - dr * (1.0f / 64.0f) + zdot;
            }
        }
        __syncthreads();
        // ---- 5: warp1 y-stat + arriveY ; tid0 waits x-stats
        if (tid >= 32 && tid < 64) {
            int l = tid - 32;
            float v0 = ys[2 * l], v1 = ys[2 * l + 1];
            float s1 = v0 + v1;
            float s2 = fmaf(v0, v0, v1 * v1);
            for (int o = 16; o > 0; o >>= 1) {
                s1 += __shfl_xor_sync(0xffffffffu, s1, o);
                s2 += __shfl_xor_sync(0xffffffffu, s2, o);
            }
            if (l == 0) {
                int sh = bk & 7;
                atomicAdd(&g_sum[s][0][100 * FS + sh], s1);
                atomicAdd(&g_ss2[s][0][100 * FS + sh], s2);
                arrive8(g_arrY[s]);
            }
        }
        if (tid == 0) wait8(g_arr[base + 0]);
        __syncthreads();
        // ---- 6: BN0 affine (x features) + apply x cols as dup pairs
        make_affine(g_sum[s][0], g_ss2[s][0], g0 + s*101, b0 + s*101, 100, affA, affC);
        __syncthreads();
        if (fA < 100) {
            float a = affA[fA], c = affC[fA];
#pragma unroll
            for (int i = 0; i < 16; i++) {
                int r = rbA + 4 * i;
                float v = fmaf(a, xs[r * XP + fA], c);
                *(float2*)&hA2[r * HP2 + 2 * fA] = make_float2(v, v);
            }
        }
        __syncthreads();
        // ---- 7: GEMM0 main (k<100) || y-path waits+applies col 100
        unsigned long long acc[4][4] = {};
        if (tid < 256) {
            gemm_main<100, 110>(acc, hA2, wb);
        } else if (tid < 320) {
            int t = tid - 256;
            wait8(g_arrY[s]);
            float a, c;
            affine_one(g_sum[s][0], g_ss2[s][0], g0[s*101 + 100], b0[s*101 + 100], 100, &a, &c);
            float v = fmaf(a, ys[t], c);
            *(float2*)&hA2[t * HP2 + 200] = make_float2(v, v);
        }
        __syncthreads();
        // ---- 8: GEMM0 tail k=100 + store
        if (tid < 256) {
            gemm_k(acc, hA2, wb + 100 * 110, (tid >> 4) * 4, tid & 15, 100);
            gemm_store<110>(acc, hB);
        }
        __syncthreads();
        // ---- 9: stats1 || copy w1 into wb
        if (tid < 128) stats128(hB, HP, 110, g_sum[s][1], g_ss2[s][1]);
        else if (tid >= 256) {
            const float4* src = (const float4*)(w1 + (size_t)s * 12100);
            float4* dst = (float4*)wb;
#pragma unroll
            for (int i = 0; i < 12; i++) {
                int idx = (tid - 256) + i * 256;
                if (idx < 3025) dst[idx] = src[idx];
            }
        }
        __syncthreads();
        if (tid == 0) { arrive8(g_arr[base + 1]); wait8(g_arr[base + 1]); }
        __syncthreads();
        // ---- Phase C: BN1+relu, GEMM1, stats2 || copy w2
        make_affine(g_sum[s][1], g_ss2[s][1], g1 + s*110, b1 + s*110, 110, affA, affC);
        __syncthreads();
        if (fA < 110) {
            float a = affA[fA], c = affC[fA];
#pragma unroll
            for (int i = 0; i < 16; i++) {
                int r = rbA + 4 * i;
                float v = fmaxf(fmaf(a, hB[r * HP + fA], c), 0.f);
                *(float2*)&hA2[r * HP2 + 2 * fA] = make_float2(v, v);
            }
        }
        __syncthreads();
        if (tid < 256) gemm64<110, 110>(hA2, wb, hB);
        __syncthreads();
        if (tid < 128) stats128(hB, HP, 110, g_sum[s][2], g_ss2[s][2]);
        else if (tid >= 256) {
            const float4* src = (const float4*)(w2 + (size_t)s * 11000);
            float4* dst = (float4*)wb;
#pragma unroll
            for (int i = 0; i < 11; i++) {
                int idx = (tid - 256) + i * 256;
                if (idx < 2750) dst[idx] = src[idx];
            }
        }
        __syncthreads();
        if (tid == 0) { arrive8(g_arr[base + 2]); wait8(g_arr[base + 2]); }
        __syncthreads();
        // ---- Phase D: BN2+relu, GEMM2 || prefetch W, stats3, arrive (no wait)
        make_affine(g_sum[s][2], g_ss2[s][2], g2 + s*110, b2 + s*110, 110, affA, affC);
        __syncthreads();
        if (fA < 110) {
            float a = affA[fA], c = affC[fA];
#pragma unroll
            for (int i = 0; i < 16; i++) {
                int r = rbA + 4 * i;
                float v = fmaxf(fmaf(a, hB[r * HP + fA], c), 0.f);
                *(float2*)&hA2[r * HP2 + 2 * fA] = make_float2(v, v);
            }
        }
        __syncthreads();
        if (tid < 256) gemm64<110, 100>(hA2, wb, hB);
        else if (s <= 61) prefetch_W256(Wc + (s & 1) * WSTR, W, row0, s + 2);
        __syncthreads();
        if (tid < 128) stats128(hB, HP, 100, g_sum[s][3], g_ss2[s][3]);
        __syncthreads();
        if (tid == 0) arrive8(g_arr[base + 3]);
    }

    // ---- Final extra step; write outputs
    if (tid == 0) wait8(g_arr[62 * 4 + 3]);
    __syncthreads();
    make_affine(g_sum[62][3], g_ss2[62][3], g3 + 62*100, b3 + 62*100, 100, affA, affC);
    __syncthreads();
    {
        float ec = expf(-0.3f * (1.0f - 62.0f / 64.0f));
        float yold = ys[r_];
        const float* Wold = Wc + r_ * 100;
        const float* Wnew = Wc + WSTR + r_ * 100;
        float ssin = 0.f, zdot = 0.f;
        for (int d = q_; d < 100; d += 8) {
            float dw = Wnew[d] - Wold[d];
            float xn = fmaf(0.3f * dw, yold, xs[r_ * XP + d]);
            out[(size_t)(row0 + r_) * 100 + d] = xn;
            ssin += my_sin(xn);
            float zv = fmaf(affA[d], hB[r_ * HP + d], affC[d]) * 0.01f;
            zdot = fmaf(zv, dw, zdot);
        }
        ssin += __shfl_xor_sync(0xffffffffu, ssin, 1);
        ssin += __shfl_xor_sync(0xffffffffu, ssin, 2);
        ssin += __shfl_xor_sync(0xffffffffu, ssin, 4);
        zdot += __shfl_xor_sync(0xffffffffu, zdot, 1);
        zdot += __shfl_xor_sync(0xffffffffu, zdot, 2);
        zdot += __shfl_xor_sync(0xffffffffu, zdot, 4);
        if (q_ == 0) {
            float tc = 0.1f * ssin;
            float dr = fmaf(-0.1f, yold, 0.045f * ec * tc * tc * tc);
            out[(size_t)8192 * 100 + row0 + r_] = yold - dr * (1.0f / 64.0f) + zdot;
        }
    }
}

extern "C" void kernel_launch(void* const* d_in, const int* in_sizes, int n_in,
                              void* d_out, int out_size) {
    cudaFuncSetAttribute(fullnn, cudaFuncAttributeMaxDynamicSharedMemorySize, SMEM_BYTES);
    fullnn<<<NBLK, NTH, SMEM_BYTES>>>(
        (const float*)d_in[0], (const float*)d_in[1], (const float*)d_in[2],
        (const float*)d_in[3], (const float*)d_in[4], (const float*)d_in[5],
        (const float*)d_in[6], (const float*)d_in[7], (const float*)d_in[8],
        (const float*)d_in[9], (const float*)d_in[10], (const float*)d_in[11],
        (const float*)d_in[12], (const float*)d_in[13],
        (float*)d_out);
}